// round 14
// baseline (speedup 1.0000x reference)
#include <cuda_runtime.h>
#include <math.h>

#define B_   4
#define C_   16
#define T_   32
#define HW_  4096
#define BC_  64
#define EPS_ 1e-10f
#define SCALE_ 0.8408964152537145f   // 2^-0.25

typedef unsigned long long u64;

// ---------------- scratch (device globals) ----------------
__device__ float  g_S   [B_][32][HW_];     // sqrt(softmax_d(qs)+eps)
__device__ float  g_qkvt[BC_][6][T_];      // qt0,qt1,kt0,kt1,vt0,vt1
__device__ float  g_zp  [BC_][4][2];       // per-chunk expsum partials of ks
__device__ float  g_cnp [BC_][4][4];       // per-chunk Cn partials
__device__ float  g_sqt [B_][32][T_];      // SCALE*sqrt(qt'+eps)
__device__ float  g_A   [B_][2][32][16];   // [b][{s,t}][cd][c']

// ---------------- helpers ----------------
__device__ __forceinline__ float warpSumAll(float v) {
#pragma unroll
    for (int o = 16; o > 0; o >>= 1) v += __shfl_xor_sync(0xffffffffu, v, o);
    return v;
}
__device__ __forceinline__ float warpMaxAll(float v) {
#pragma unroll
    for (int o = 16; o > 0; o >>= 1) v = fmaxf(v, __shfl_xor_sync(0xffffffffu, v, o));
    return v;
}
__device__ __forceinline__ float blockSum256(float v) {
    __shared__ float red[8];
    int lane = threadIdx.x & 31, wid = threadIdx.x >> 5;
    float s = warpSumAll(v);
    __syncthreads();
    if (lane == 0) red[wid] = s;
    __syncthreads();
    float r = red[0];
#pragma unroll
    for (int w = 1; w < 8; w++) r += red[w];
    return r;
}
__device__ __forceinline__ u64 pack2(float lo, float hi) {
    u64 r; asm("mov.b64 %0, {%1, %2};" : "=l"(r) : "f"(lo), "f"(hi)); return r;
}
__device__ __forceinline__ u64 fma2(u64 a, u64 b, u64 c) {
    u64 d; asm("fma.rn.f32x2 %0, %1, %2, %3;" : "=l"(d) : "l"(a), "l"(b), "l"(c)); return d;
}
__device__ __forceinline__ float2 unpk2(u64 v) {
    float2 f; asm("mov.b64 {%0, %1}, %2;" : "=f"(f.x), "=f"(f.y) : "l"(v)); return f;
}
__device__ __forceinline__ float sqrt_ap(float x) {
    float r; asm("sqrt.approx.f32 %0, %1;" : "=f"(r) : "f"(x)); return r;
}
__device__ __forceinline__ float rcp_ap(float x) {
    float r; asm("rcp.approx.f32 %0, %1;" : "=f"(r) : "f"(x)); return r;
}
__device__ __forceinline__ float rsqrt_ap(float x) {
    float r; asm("rsqrt.approx.f32 %0, %1;" : "=f"(r) : "f"(x)); return r;
}

// ---------------- K1 (fused): y<4 spatial proj + S + stats; y>=4 temporal proj ----------------
__global__ __launch_bounds__(256) void k1(const float* __restrict__ x,
                                          const float* __restrict__ wqs,
                                          const float* __restrict__ wqt) {
    int bc = blockIdx.x;
    int j  = threadIdx.x;

    if (blockIdx.y < 4) {
        int chunk = blockIdx.y;
        int n0 = chunk * 1024 + j * 4;
        __shared__ u64 ws2[192];
        if (j < 192) { float w = wqs[j]; ws2[j] = pack2(w, w); }
        __syncthreads();

        const float* xs = x + (size_t)bc * T_ * HW_;
        u64 acc[6][2];
#pragma unroll
        for (int k = 0; k < 6; k++) { acc[k][0] = 0ull; acc[k][1] = 0ull; }

#pragma unroll
        for (int tb = 0; tb < 4; tb++) {
            ulonglong2 xv[8];   // direct f32x2 pairs -- no pack movs
#pragma unroll
            for (int u = 0; u < 8; u++)
                xv[u] = *(const ulonglong2*)&xs[(size_t)(tb * 8 + u) * HW_ + n0];
#pragma unroll
            for (int u = 0; u < 8; u++) {
                int t = tb * 8 + u;
#pragma unroll
                for (int k = 0; k < 6; k++) {
                    u64 w = ws2[k * 32 + t];
                    acc[k][0] = fma2(xv[u].x, w, acc[k][0]);
                    acc[k][1] = fma2(xv[u].y, w, acc[k][1]);
                }
            }
        }

        float col[6][4];
#pragma unroll
        for (int k = 0; k < 6; k++) {
            float2 a = unpk2(acc[k][0]), b2 = unpk2(acc[k][1]);
            col[k][0] = a.x; col[k][1] = a.y; col[k][2] = b2.x; col[k][3] = b2.y;
        }

        int b = bc >> 4, c = bc & 15;
        float so0[4], so1[4];
#pragma unroll
        for (int m = 0; m < 4; m++) {
            float q0 = col[0][m], q1 = col[1][m];
            float mx = fmaxf(q0, q1);
            float e0 = __expf(q0 - mx), e1 = __expf(q1 - mx);
            float inv = rcp_ap(e0 + e1);
            so0[m] = sqrt_ap(e0 * inv + EPS_);
            so1[m] = sqrt_ap(e1 * inv + EPS_);
        }
        *(float4*)&g_S[b][2 * c][n0]     = make_float4(so0[0], so0[1], so0[2], so0[3]);
        *(float4*)&g_S[b][2 * c + 1][n0] = make_float4(so1[0], so1[1], so1[2], so1[3]);

        float z0 = 0.f, z1 = 0.f;
        float cn00 = 0, cn01 = 0, cn10 = 0, cn11 = 0;
#pragma unroll
        for (int m = 0; m < 4; m++) {
            float e0 = __expf(col[2][m]);
            float e1 = __expf(col[3][m]);
            z0 += e0; z1 += e1;
            float va = col[4][m], vb = col[5][m];
            cn00 += sqrt_ap(e0 * va); cn01 += sqrt_ap(e0 * vb);
            cn10 += sqrt_ap(e1 * va); cn11 += sqrt_ap(e1 * vb);
        }
        z0   = blockSum256(z0);   z1   = blockSum256(z1);
        cn00 = blockSum256(cn00); cn01 = blockSum256(cn01);
        cn10 = blockSum256(cn10); cn11 = blockSum256(cn11);
        if (j == 0) {
            g_zp[bc][chunk][0] = z0; g_zp[bc][chunk][1] = z1;
            g_cnp[bc][chunk][0] = cn00; g_cnp[bc][chunk][1] = cn01;
            g_cnp[bc][chunk][2] = cn10; g_cnp[bc][chunk][3] = cn11;
        }
    } else {
        // ---- temporal: 4 t per block, vectorized float4 over n ----
        int t0 = (blockIdx.y - 4) * 4;
        const float* xs = x + (size_t)bc * T_ * HW_ + (size_t)t0 * HW_;
        float acc[6][4];
#pragma unroll
        for (int k = 0; k < 6; k++)
#pragma unroll
            for (int tt = 0; tt < 4; tt++) acc[k][tt] = 0.f;

#pragma unroll
        for (int i = 0; i < 4; i++) {
            int n0 = i * 1024 + j * 4;
            float4 wv[6];
#pragma unroll
            for (int k = 0; k < 6; k++) wv[k] = *(const float4*)&wqt[k * HW_ + n0];
            float4 xv[4];
#pragma unroll
            for (int tt = 0; tt < 4; tt++)
                xv[tt] = *(const float4*)&xs[(size_t)tt * HW_ + n0];
#pragma unroll
            for (int tt = 0; tt < 4; tt++) {
#pragma unroll
                for (int k = 0; k < 6; k++) {
                    acc[k][tt] += xv[tt].x * wv[k].x + xv[tt].y * wv[k].y
                                + xv[tt].z * wv[k].z + xv[tt].w * wv[k].w;
                }
            }
        }

        __shared__ float wpart[8][24];
        int lane = j & 31, wid = j >> 5;
#pragma unroll
        for (int k = 0; k < 6; k++)
#pragma unroll
            for (int tt = 0; tt < 4; tt++) {
                float v = warpSumAll(acc[k][tt]);
                if (lane == 0) wpart[wid][k * 4 + tt] = v;
            }
        __syncthreads();
        if (j < 24) {
            float s = 0.f;
#pragma unroll
            for (int w = 0; w < 8; w++) s += wpart[w][j];
            g_qkvt[bc][j >> 2][t0 + (j & 3)] = s;
        }
    }
}

// ---------------- K2fin: t-side softmaxes, sqt, ctx, A ----------------
__global__ __launch_bounds__(64) void k2fin(const float* __restrict__ wos,
                                            const float* __restrict__ wot) {
    int bc = blockIdx.x;
    int b = bc >> 4, c = bc & 15;
    int tid = threadIdx.x;
    __shared__ float ctx_sh[4];

    if (tid < 32) {
        int t = tid;
        float q0 = g_qkvt[bc][0][t], q1 = g_qkvt[bc][1][t];
        float mx = fmaxf(q0, q1);
        float e0 = __expf(q0 - mx), e1 = __expf(q1 - mx);
        float inv = rcp_ap(e0 + e1);
        g_sqt[b][2 * c][t]     = SCALE_ * sqrt_ap(e0 * inv + EPS_);
        g_sqt[b][2 * c + 1][t] = SCALE_ * sqrt_ap(e1 * inv + EPS_);

        float k0 = g_qkvt[bc][2][t], k1v = g_qkvt[bc][3][t];
        float M0 = warpMaxAll(k0), M1 = warpMaxAll(k1v);
        float x0 = __expf(k0 - M0), x1 = __expf(k1v - M1);
        float Zi0 = rcp_ap(warpSumAll(x0)), Zi1 = rcp_ap(warpSumAll(x1));
        float kt0 = x0 * Zi0 + EPS_, kt1 = x1 * Zi1 + EPS_;
        float vt0 = g_qkvt[bc][4][t], vt1 = g_qkvt[bc][5][t];
        float c00 = warpSumAll(sqrt_ap(kt0 * vt0));
        float c01 = warpSumAll(sqrt_ap(kt0 * vt1));
        float c10 = warpSumAll(sqrt_ap(kt1 * vt0));
        float c11 = warpSumAll(sqrt_ap(kt1 * vt1));
        if (t == 0) {
            float Z0 = 0.f, Z1 = 0.f, cns[4] = {0.f, 0.f, 0.f, 0.f};
#pragma unroll
            for (int ch = 0; ch < 4; ch++) {
                Z0 += g_zp[bc][ch][0];
                Z1 += g_zp[bc][ch][1];
#pragma unroll
                for (int i = 0; i < 4; i++) cns[i] += g_cnp[bc][ch][i];
            }
            float r0 = rsqrt_ap(Z0), r1 = rsqrt_ap(Z1);
            ctx_sh[0] = SCALE_ * c00 * cns[0] * r0;
            ctx_sh[1] = SCALE_ * c01 * cns[1] * r0;
            ctx_sh[2] = SCALE_ * c10 * cns[2] * r1;
            ctx_sh[3] = SCALE_ * c11 * cns[3] * r1;
        }
    }
    __syncthreads();

    int st = tid >> 5, d = (tid >> 4) & 1, cp = tid & 15;
    const float* w = st ? wot : wos;
    float x0 = ctx_sh[2 * d], x1 = ctx_sh[2 * d + 1];
    g_A[b][st][2 * c + d][cp] = w[cp * 32 + 2 * c] * x0 + w[cp * 32 + 2 * c + 1] * x1;
}

// ---------------- K3: out[c',t,n] = sqrt( (Gs.S)*(Gt.S) ) ----------------
// grid (64 ntiles of 64 n, 4 b, 8 tchunks of 4 t) = 2048 blocks. 256 thr = (cg 8 warps, ng 32).
// G = A*sqt prebuilt in smem ONCE per block for its 4 t -> mainloop is pure fma2:
// per cd: 1 per-lane LDS.64 + 8 bcast LDS.128 + 16 fma2 (all useful). acc = 16 u64 = 32 regs.
__global__ __launch_bounds__(256, 3) void k3(float* __restrict__ out) {
    int nt = blockIdx.x, b = blockIdx.y, tc = blockIdx.z;
    int n0 = nt * 64;
    int j = threadIdx.x;

    __shared__ u64 S2[32][32];        // 8 KB  : S pairs along n (row cd)
    __shared__ u64 Gd[4][32][8][4];   // 32 KB : [tt][cd][cg]{Gs0,Gs1,Gt0,Gt1} dup

#pragma unroll
    for (int u = 0; u < 2; u++) {
        int idx = u * 256 + j;
        int r = idx >> 4, q = idx & 15;
        *(float4*)&S2[r][q * 2] = ((const float4*)&g_S[b][r][n0])[q];
    }
    {
        int cd = j >> 3, cg = j & 7;
        float As0 = g_A[b][0][cd][cg * 2], As1 = g_A[b][0][cd][cg * 2 + 1];
        float At0 = g_A[b][1][cd][cg * 2], At1 = g_A[b][1][cd][cg * 2 + 1];
#pragma unroll
        for (int tt = 0; tt < 4; tt++) {
            float q = g_sqt[b][cd][tc * 4 + tt];
            float v0 = As0 * q, v1 = As1 * q, v2 = At0 * q, v3 = At1 * q;
            ulonglong2 w0, w1;
            w0.x = pack2(v0, v0); w0.y = pack2(v1, v1);
            w1.x = pack2(v2, v2); w1.y = pack2(v3, v3);
            *(ulonglong2*)&Gd[tt][cd][cg][0] = w0;
            *(ulonglong2*)&Gd[tt][cd][cg][2] = w1;
        }
    }
    __syncthreads();

    int cg = j >> 5, ng = j & 31;

    u64 acc[4][4];   // [{s0,s1,t0,t1}][tt] : 16 u64 = 32 regs
#pragma unroll
    for (int a = 0; a < 4; a++)
#pragma unroll
        for (int tt = 0; tt < 4; tt++) acc[a][tt] = 0ull;

#pragma unroll 8
    for (int cd = 0; cd < 32; cd++) {
        u64 sp = S2[cd][ng];    // per-lane, 2 n
#pragma unroll
        for (int tt = 0; tt < 4; tt++) {
            ulonglong2 g01 = *(const ulonglong2*)&Gd[tt][cd][cg][0];  // bcast Gs
            ulonglong2 g23 = *(const ulonglong2*)&Gd[tt][cd][cg][2];  // bcast Gt
            acc[0][tt] = fma2(g01.x, sp, acc[0][tt]);
            acc[1][tt] = fma2(g01.y, sp, acc[1][tt]);
            acc[2][tt] = fma2(g23.x, sp, acc[2][tt]);
            acc[3][tt] = fma2(g23.y, sp, acc[3][tt]);
        }
    }

#pragma unroll
    for (int pc = 0; pc < 2; pc++) {
        int cp = cg * 2 + pc;
#pragma unroll
        for (int tt = 0; tt < 4; tt++) {
            float2 s = unpk2(acc[pc][tt]);
            float2 t = unpk2(acc[2 + pc][tt]);
            float2 o;
            o.x = sqrt_ap(s.x * t.x);
            o.y = sqrt_ap(s.y * t.y);
            int tglob = tc * 4 + tt;
            *(float2*)&out[(((size_t)(b * 16 + cp) * T_ + tglob) * HW_) + n0 + ng * 2] = o;
        }
    }
}

// ---------------- launch ----------------
extern "C" void kernel_launch(void* const* d_in, const int* in_sizes, int n_in,
                              void* d_out, int out_size) {
    const float* x   = (const float*)d_in[0];
    const float* wqs = (const float*)d_in[1];
    const float* wqt = (const float*)d_in[2];
    const float* wos = (const float*)d_in[3];
    const float* wot = (const float*)d_in[4];
    float* out = (float*)d_out;

    k1   <<<dim3(BC_, 12), 256>>>(x, wqs, wqt);
    k2fin<<<BC_, 64>>>(wos, wot);
    k3   <<<dim3(64, B_, 8), 256>>>(out);
}

// round 15
// speedup vs baseline: 1.2502x; 1.2502x over previous
#include <cuda_runtime.h>
#include <math.h>

#define B_   4
#define C_   16
#define T_   32
#define HW_  4096
#define BC_  64
#define EPS_ 1e-10f
#define SCALE_ 0.8408964152537145f   // 2^-0.25

typedef unsigned long long u64;

// ---------------- scratch (device globals) ----------------
__device__ float  g_S   [B_][32][HW_];     // sqrt(softmax_d(qs)+eps)
__device__ float  g_qkvt[BC_][6][T_];      // qt0,qt1,kt0,kt1,vt0,vt1
__device__ float  g_zp  [BC_][4][2];       // per-chunk expsum partials of ks
__device__ float  g_cnp [BC_][4][4];       // per-chunk Cn partials
__device__ float  g_sqt [B_][32][T_];      // SCALE*sqrt(qt'+eps)
__device__ float  g_A   [B_][2][32][16];   // [b][{s,t}][cd][c']

// ---------------- helpers ----------------
__device__ __forceinline__ float warpSumAll(float v) {
#pragma unroll
    for (int o = 16; o > 0; o >>= 1) v += __shfl_xor_sync(0xffffffffu, v, o);
    return v;
}
__device__ __forceinline__ float warpMaxAll(float v) {
#pragma unroll
    for (int o = 16; o > 0; o >>= 1) v = fmaxf(v, __shfl_xor_sync(0xffffffffu, v, o));
    return v;
}
__device__ __forceinline__ float blockSum256(float v) {
    __shared__ float red[8];
    int lane = threadIdx.x & 31, wid = threadIdx.x >> 5;
    float s = warpSumAll(v);
    __syncthreads();
    if (lane == 0) red[wid] = s;
    __syncthreads();
    float r = red[0];
#pragma unroll
    for (int w = 1; w < 8; w++) r += red[w];
    return r;
}
__device__ __forceinline__ u64 pack2(float lo, float hi) {
    u64 r; asm("mov.b64 %0, {%1, %2};" : "=l"(r) : "f"(lo), "f"(hi)); return r;
}
__device__ __forceinline__ u64 fma2(u64 a, u64 b, u64 c) {
    u64 d; asm("fma.rn.f32x2 %0, %1, %2, %3;" : "=l"(d) : "l"(a), "l"(b), "l"(c)); return d;
}
__device__ __forceinline__ u64 mul2(u64 a, u64 b) {
    u64 d; asm("mul.rn.f32x2 %0, %1, %2;" : "=l"(d) : "l"(a), "l"(b)); return d;
}
__device__ __forceinline__ float2 unpk2(u64 v) {
    float2 f; asm("mov.b64 {%0, %1}, %2;" : "=f"(f.x), "=f"(f.y) : "l"(v)); return f;
}
__device__ __forceinline__ float sqrt_ap(float x) {
    float r; asm("sqrt.approx.f32 %0, %1;" : "=f"(r) : "f"(x)); return r;
}
__device__ __forceinline__ float rcp_ap(float x) {
    float r; asm("rcp.approx.f32 %0, %1;" : "=f"(r) : "f"(x)); return r;
}
__device__ __forceinline__ float rsqrt_ap(float x) {
    float r; asm("rsqrt.approx.f32 %0, %1;" : "=f"(r) : "f"(x)); return r;
}

// ---------------- K1 (fused): y<4 spatial proj + S + stats; y>=4 temporal proj ----------------
__global__ __launch_bounds__(256) void k1(const float* __restrict__ x,
                                          const float* __restrict__ wqs,
                                          const float* __restrict__ wqt) {
    int bc = blockIdx.x;
    int j  = threadIdx.x;

    if (blockIdx.y < 4) {
        int chunk = blockIdx.y;
        int n0 = chunk * 1024 + j * 4;
        __shared__ u64 ws2[192];
        if (j < 192) { float w = wqs[j]; ws2[j] = pack2(w, w); }
        __syncthreads();

        const float* xs = x + (size_t)bc * T_ * HW_;
        u64 acc[6][2];
#pragma unroll
        for (int k = 0; k < 6; k++) { acc[k][0] = 0ull; acc[k][1] = 0ull; }

#pragma unroll
        for (int tb = 0; tb < 4; tb++) {
            ulonglong2 xv[8];   // direct f32x2 pairs -- no pack movs
#pragma unroll
            for (int u = 0; u < 8; u++)
                xv[u] = *(const ulonglong2*)&xs[(size_t)(tb * 8 + u) * HW_ + n0];
#pragma unroll
            for (int u = 0; u < 8; u++) {
                int t = tb * 8 + u;
#pragma unroll
                for (int k = 0; k < 6; k++) {
                    u64 w = ws2[k * 32 + t];
                    acc[k][0] = fma2(xv[u].x, w, acc[k][0]);
                    acc[k][1] = fma2(xv[u].y, w, acc[k][1]);
                }
            }
        }

        float col[6][4];
#pragma unroll
        for (int k = 0; k < 6; k++) {
            float2 a = unpk2(acc[k][0]), b2 = unpk2(acc[k][1]);
            col[k][0] = a.x; col[k][1] = a.y; col[k][2] = b2.x; col[k][3] = b2.y;
        }

        int b = bc >> 4, c = bc & 15;
        float so0[4], so1[4];
#pragma unroll
        for (int m = 0; m < 4; m++) {
            float q0 = col[0][m], q1 = col[1][m];
            float mx = fmaxf(q0, q1);
            float e0 = __expf(q0 - mx), e1 = __expf(q1 - mx);
            float inv = rcp_ap(e0 + e1);
            so0[m] = sqrt_ap(e0 * inv + EPS_);
            so1[m] = sqrt_ap(e1 * inv + EPS_);
        }
        *(float4*)&g_S[b][2 * c][n0]     = make_float4(so0[0], so0[1], so0[2], so0[3]);
        *(float4*)&g_S[b][2 * c + 1][n0] = make_float4(so1[0], so1[1], so1[2], so1[3]);

        float z0 = 0.f, z1 = 0.f;
        float cn00 = 0, cn01 = 0, cn10 = 0, cn11 = 0;
#pragma unroll
        for (int m = 0; m < 4; m++) {
            float e0 = __expf(col[2][m]);
            float e1 = __expf(col[3][m]);
            z0 += e0; z1 += e1;
            float va = col[4][m], vb = col[5][m];
            cn00 += sqrt_ap(e0 * va); cn01 += sqrt_ap(e0 * vb);
            cn10 += sqrt_ap(e1 * va); cn11 += sqrt_ap(e1 * vb);
        }
        z0   = blockSum256(z0);   z1   = blockSum256(z1);
        cn00 = blockSum256(cn00); cn01 = blockSum256(cn01);
        cn10 = blockSum256(cn10); cn11 = blockSum256(cn11);
        if (j == 0) {
            g_zp[bc][chunk][0] = z0; g_zp[bc][chunk][1] = z1;
            g_cnp[bc][chunk][0] = cn00; g_cnp[bc][chunk][1] = cn01;
            g_cnp[bc][chunk][2] = cn10; g_cnp[bc][chunk][3] = cn11;
        }
    } else {
        // ---- temporal: 4 t per block, vectorized float4 over n ----
        int t0 = (blockIdx.y - 4) * 4;
        const float* xs = x + (size_t)bc * T_ * HW_ + (size_t)t0 * HW_;
        float acc[6][4];
#pragma unroll
        for (int k = 0; k < 6; k++)
#pragma unroll
            for (int tt = 0; tt < 4; tt++) acc[k][tt] = 0.f;

#pragma unroll
        for (int i = 0; i < 4; i++) {
            int n0 = i * 1024 + j * 4;
            float4 wv[6];
#pragma unroll
            for (int k = 0; k < 6; k++) wv[k] = *(const float4*)&wqt[k * HW_ + n0];
            float4 xv[4];
#pragma unroll
            for (int tt = 0; tt < 4; tt++)
                xv[tt] = *(const float4*)&xs[(size_t)tt * HW_ + n0];
#pragma unroll
            for (int tt = 0; tt < 4; tt++) {
#pragma unroll
                for (int k = 0; k < 6; k++) {
                    acc[k][tt] += xv[tt].x * wv[k].x + xv[tt].y * wv[k].y
                                + xv[tt].z * wv[k].z + xv[tt].w * wv[k].w;
                }
            }
        }

        __shared__ float wpart[8][24];
        int lane = j & 31, wid = j >> 5;
#pragma unroll
        for (int k = 0; k < 6; k++)
#pragma unroll
            for (int tt = 0; tt < 4; tt++) {
                float v = warpSumAll(acc[k][tt]);
                if (lane == 0) wpart[wid][k * 4 + tt] = v;
            }
        __syncthreads();
        if (j < 24) {
            float s = 0.f;
#pragma unroll
            for (int w = 0; w < 8; w++) s += wpart[w][j];
            g_qkvt[bc][j >> 2][t0 + (j & 3)] = s;
        }
    }
}

// ---------------- K2fin: t-side softmaxes, sqt, ctx, A ----------------
__global__ __launch_bounds__(64) void k2fin(const float* __restrict__ wos,
                                            const float* __restrict__ wot) {
    int bc = blockIdx.x;
    int b = bc >> 4, c = bc & 15;
    int tid = threadIdx.x;
    __shared__ float ctx_sh[4];

    if (tid < 32) {
        int t = tid;
        float q0 = g_qkvt[bc][0][t], q1 = g_qkvt[bc][1][t];
        float mx = fmaxf(q0, q1);
        float e0 = __expf(q0 - mx), e1 = __expf(q1 - mx);
        float inv = rcp_ap(e0 + e1);
        g_sqt[b][2 * c][t]     = SCALE_ * sqrt_ap(e0 * inv + EPS_);
        g_sqt[b][2 * c + 1][t] = SCALE_ * sqrt_ap(e1 * inv + EPS_);

        float k0 = g_qkvt[bc][2][t], k1v = g_qkvt[bc][3][t];
        float M0 = warpMaxAll(k0), M1 = warpMaxAll(k1v);
        float x0 = __expf(k0 - M0), x1 = __expf(k1v - M1);
        float Zi0 = rcp_ap(warpSumAll(x0)), Zi1 = rcp_ap(warpSumAll(x1));
        float kt0 = x0 * Zi0 + EPS_, kt1 = x1 * Zi1 + EPS_;
        float vt0 = g_qkvt[bc][4][t], vt1 = g_qkvt[bc][5][t];
        float c00 = warpSumAll(sqrt_ap(kt0 * vt0));
        float c01 = warpSumAll(sqrt_ap(kt0 * vt1));
        float c10 = warpSumAll(sqrt_ap(kt1 * vt0));
        float c11 = warpSumAll(sqrt_ap(kt1 * vt1));
        if (t == 0) {
            float Z0 = 0.f, Z1 = 0.f, cns[4] = {0.f, 0.f, 0.f, 0.f};
#pragma unroll
            for (int ch = 0; ch < 4; ch++) {
                Z0 += g_zp[bc][ch][0];
                Z1 += g_zp[bc][ch][1];
#pragma unroll
                for (int i = 0; i < 4; i++) cns[i] += g_cnp[bc][ch][i];
            }
            float r0 = rsqrt_ap(Z0), r1 = rsqrt_ap(Z1);
            ctx_sh[0] = SCALE_ * c00 * cns[0] * r0;
            ctx_sh[1] = SCALE_ * c01 * cns[1] * r0;
            ctx_sh[2] = SCALE_ * c10 * cns[2] * r1;
            ctx_sh[3] = SCALE_ * c11 * cns[3] * r1;
        }
    }
    __syncthreads();

    int st = tid >> 5, d = (tid >> 4) & 1, cp = tid & 15;
    const float* w = st ? wot : wos;
    float x0 = ctx_sh[2 * d], x1 = ctx_sh[2 * d + 1];
    g_A[b][st][2 * c + d][cp] = w[cp * 32 + 2 * c] * x0 + w[cp * 32 + 2 * c + 1] * x1;
}

// ---------------- K3: out[c',t,n] = sqrt( (Gs.S)*(Gt.S) ), G = A * sqt[t] ----------------
// grid (32 ntiles of 128 n, 4 b, 16 tchunks of 2 t) = 2048 blocks. 256 thr = (cg 8 warps, ng 32).
// Thread tile: 2 c' x 4 n (2 u64, one LDS.128) x 2 t x 2 branches; acc = 16 u64 = 32 regs.
// Per cd: 1 per-lane LDS.128 + 3 bcast LDS, 4 mul2 + 16 fma2. Epilogue: 4 STG.128.
__global__ __launch_bounds__(256, 3) void k3(float* __restrict__ out) {
    int nt = blockIdx.x, b = blockIdx.y, tc = blockIdx.z;
    int n0 = nt * 128;
    int j = threadIdx.x;

    __shared__ u64 S2[32][64];      // 16 KB : S pairs along n (row cd, 128 n)
    __shared__ u64 Ad[32][8][4];    // 8 KB  : [cd][cg]{As0,As1,At0,At1} dup
    __shared__ u64 qd[32][2];       // 512 B : dup sqt for this tchunk's 2 t

#pragma unroll
    for (int u = 0; u < 4; u++) {
        int idx = u * 256 + j;          // 1024 float4s = 4096 floats
        int r = idx >> 5, q = idx & 31;
        *(float4*)&S2[r][q * 2] = ((const float4*)&g_S[b][r][n0])[q];
    }
    {
        int cd = j >> 3, cg = j & 7;
        float s0 = g_A[b][0][cd][cg * 2], s1 = g_A[b][0][cd][cg * 2 + 1];
        float t0 = g_A[b][1][cd][cg * 2], t1 = g_A[b][1][cd][cg * 2 + 1];
        Ad[cd][cg][0] = pack2(s0, s0); Ad[cd][cg][1] = pack2(s1, s1);
        Ad[cd][cg][2] = pack2(t0, t0); Ad[cd][cg][3] = pack2(t1, t1);
    }
    if (j < 64) {
        int cd = j >> 1, tt = j & 1;
        float a = g_sqt[b][cd][tc * 2 + tt];
        qd[cd][tt] = pack2(a, a);
    }
    __syncthreads();

    int cg = j >> 5, ng = j & 31;

    u64 acc[4][2][2];   // [{s0,s1,t0,t1}][tt][nu] : 16 u64 = 32 regs
#pragma unroll
    for (int a = 0; a < 4; a++)
#pragma unroll
        for (int tt = 0; tt < 2; tt++) { acc[a][tt][0] = 0ull; acc[a][tt][1] = 0ull; }

#pragma unroll 8
    for (int cd = 0; cd < 32; cd++) {
        ulonglong2 sp  = *(const ulonglong2*)&S2[cd][ng * 2];       // per-lane, 4 n
        ulonglong2 avs = *(const ulonglong2*)&Ad[cd][cg][0];        // bcast As
        ulonglong2 avt = *(const ulonglong2*)&Ad[cd][cg][2];        // bcast At
        ulonglong2 qq  = *(const ulonglong2*)&qd[cd][0];            // bcast q t0,t1
        u64 qv[2] = {qq.x, qq.y};
#pragma unroll
        for (int tt = 0; tt < 2; tt++) {
            u64 m0 = mul2(sp.x, qv[tt]);
            u64 m1 = mul2(sp.y, qv[tt]);
            acc[0][tt][0] = fma2(avs.x, m0, acc[0][tt][0]);
            acc[0][tt][1] = fma2(avs.x, m1, acc[0][tt][1]);
            acc[1][tt][0] = fma2(avs.y, m0, acc[1][tt][0]);
            acc[1][tt][1] = fma2(avs.y, m1, acc[1][tt][1]);
            acc[2][tt][0] = fma2(avt.x, m0, acc[2][tt][0]);
            acc[2][tt][1] = fma2(avt.x, m1, acc[2][tt][1]);
            acc[3][tt][0] = fma2(avt.y, m0, acc[3][tt][0]);
            acc[3][tt][1] = fma2(avt.y, m1, acc[3][tt][1]);
        }
    }

#pragma unroll
    for (int pc = 0; pc < 2; pc++) {
        int cp = cg * 2 + pc;
#pragma unroll
        for (int tt = 0; tt < 2; tt++) {
            float2 s0 = unpk2(acc[pc][tt][0]);
            float2 s1 = unpk2(acc[pc][tt][1]);
            float2 t0 = unpk2(acc[2 + pc][tt][0]);
            float2 t1 = unpk2(acc[2 + pc][tt][1]);
            float4 o;
            o.x = sqrt_ap(s0.x * t0.x);
            o.y = sqrt_ap(s0.y * t0.y);
            o.z = sqrt_ap(s1.x * t1.x);
            o.w = sqrt_ap(s1.y * t1.y);
            int tglob = tc * 2 + tt;
            *(float4*)&out[(((size_t)(b * 16 + cp) * T_ + tglob) * HW_) + n0 + ng * 4] = o;
        }
    }
}

// ---------------- launch ----------------
extern "C" void kernel_launch(void* const* d_in, const int* in_sizes, int n_in,
                              void* d_out, int out_size) {
    const float* x   = (const float*)d_in[0];
    const float* wqs = (const float*)d_in[1];
    const float* wqt = (const float*)d_in[2];
    const float* wos = (const float*)d_in[3];
    const float* wot = (const float*)d_in[4];
    float* out = (float*)d_out;

    k1   <<<dim3(BC_, 12), 256>>>(x, wqs, wqt);
    k2fin<<<BC_, 64>>>(wos, wot);
    k3   <<<dim3(32, B_, 16), 256>>>(out);
}